// round 1
// baseline (speedup 1.0000x reference)
#include <cuda_runtime.h>

#define D 128
#define N_ING 100000
#define N_TASTE 50000
#define E_EDGES 600000
#define NEG_SLOPE 0.2f

// ---------------- scratch (device globals; no allocation allowed) ----------
__device__ float        g_v_src[D];
__device__ float        g_v_dst[D];
__device__ float        g_c_src;
__device__ float        g_c_dst;
__device__ float        g_a_src[N_ING];
__device__ float        g_a_dst[N_TASTE];
__device__ unsigned int g_seg_max[N_TASTE];   // ordered-uint float keys
__device__ float        g_seg_sum[N_TASTE];
__device__ float        g_alpha[E_EDGES];     // logits, then exp values
__device__ float        g_gbuf[(size_t)N_TASTE * D]; // Sum_e w_e * x_ing[src]  (25.6MB)

// ordered-uint encoding so atomicMax(uint) == max over floats
__device__ __forceinline__ unsigned int fkey(float f) {
    unsigned int u = __float_as_uint(f);
    return (u & 0x80000000u) ? ~u : (u | 0x80000000u);
}
__device__ __forceinline__ float fkey_inv(unsigned int k) {
    return (k & 0x80000000u) ? __uint_as_float(k ^ 0x80000000u)
                             : __uint_as_float(~k);
}

// ---------------- K0: v_src = W_ing @ att_src, v_dst = W_taste @ att_dst ----
__global__ void k0_prep(const float* __restrict__ W_ing,  const float* __restrict__ b_ing,
                        const float* __restrict__ W_taste,const float* __restrict__ b_taste,
                        const float* __restrict__ att_src,const float* __restrict__ att_dst) {
    int k = threadIdx.x;  // 128 threads
    float s1 = 0.f, s2 = 0.f;
    #pragma unroll 4
    for (int d = 0; d < D; d++) {
        s1 += W_ing[k * D + d]   * att_src[d];
        s2 += W_taste[k * D + d] * att_dst[d];
    }
    g_v_src[k] = s1;
    g_v_dst[k] = s2;
    if (k == 0) { float c = 0.f; for (int d = 0; d < D; d++) c += b_ing[d]   * att_src[d]; g_c_src = c; }
    if (k == 1) { float c = 0.f; for (int d = 0; d < D; d++) c += b_taste[d] * att_dst[d]; g_c_dst = c; }
}

// ---------------- K init: zero segment state + g buffer ----------------
__global__ void k_init() {
    int i      = blockIdx.x * blockDim.x + threadIdx.x;
    int stride = gridDim.x * blockDim.x;
    for (int j = i; j < N_TASTE; j += stride) { g_seg_max[j] = 0u; g_seg_sum[j] = 0.f; }
    float4* g4 = (float4*)g_gbuf;
    int n4 = N_TASTE * D / 4;
    for (int j = i; j < n4; j += stride) g4[j] = make_float4(0.f, 0.f, 0.f, 0.f);
}

// ---------------- K1/K2: per-node attention logits (warp per node) --------
__global__ void k_a_src(const float* __restrict__ x) {
    int warp = (blockIdx.x * blockDim.x + threadIdx.x) >> 5;
    int lane = threadIdx.x & 31;
    if (warp >= N_ING) return;
    float4 xv = ((const float4*)(x + (size_t)warp * D))[lane];
    float4 vv = ((const float4*)g_v_src)[lane];
    float s = xv.x * vv.x + xv.y * vv.y + xv.z * vv.z + xv.w * vv.w;
    #pragma unroll
    for (int o = 16; o; o >>= 1) s += __shfl_down_sync(0xffffffffu, s, o);
    if (lane == 0) g_a_src[warp] = s + g_c_src;
}

__global__ void k_a_dst(const float* __restrict__ x) {
    int warp = (blockIdx.x * blockDim.x + threadIdx.x) >> 5;
    int lane = threadIdx.x & 31;
    if (warp >= N_TASTE) return;
    float4 xv = ((const float4*)(x + (size_t)warp * D))[lane];
    float4 vv = ((const float4*)g_v_dst)[lane];
    float s = xv.x * vv.x + xv.y * vv.y + xv.z * vv.z + xv.w * vv.w;
    #pragma unroll
    for (int o = 16; o; o >>= 1) s += __shfl_down_sync(0xffffffffu, s, o);
    if (lane == 0) g_a_dst[warp] = s + g_c_dst;
}

// ---------------- K3: edge logits + segment max ----------------
__global__ void k3_logits(const int* __restrict__ src, const int* __restrict__ dst) {
    int e = blockIdx.x * blockDim.x + threadIdx.x;
    if (e >= E_EDGES) return;
    int t = dst[e];
    float l = g_a_src[src[e]] + g_a_dst[t];
    l = l > 0.f ? l : NEG_SLOPE * l;
    g_alpha[e] = l;
    atomicMax(&g_seg_max[t], fkey(l));
}

// ---------------- K4: exp + segment sum ----------------
__global__ void k4_exp(const int* __restrict__ dst) {
    int e = blockIdx.x * blockDim.x + threadIdx.x;
    if (e >= E_EDGES) return;
    int t = dst[e];
    float m = fkey_inv(g_seg_max[t]);
    float ex = expf(g_alpha[e] - m);
    g_alpha[e] = ex;
    atomicAdd(&g_seg_sum[t], ex);
}

// ---------------- K5: weighted scatter of raw x_ing rows (warp/edge) -------
__global__ void k5_scatter(const float* __restrict__ x_ing,
                           const int* __restrict__ src, const int* __restrict__ dst) {
    int gw   = (blockIdx.x * blockDim.x + threadIdx.x) >> 5;
    int lane = threadIdx.x & 31;
    int nw   = (gridDim.x * blockDim.x) >> 5;
    for (int e = gw; e < E_EDGES; e += nw) {
        int s = src[e];
        int t = dst[e];
        float w = g_alpha[e] / (g_seg_sum[t] + 1e-16f);
        float4 xv = ((const float4*)(x_ing + (size_t)s * D))[lane];
        float* gp = g_gbuf + (size_t)t * D + lane * 4;
        asm volatile("red.global.add.v4.f32 [%0], {%1,%2,%3,%4};"
                     :: "l"(gp), "f"(w * xv.x), "f"(w * xv.y), "f"(w * xv.z), "f"(w * xv.w)
                     : "memory");
    }
}

// ---------------- K6: agg = g @ W_ing + b (masked) ; fused epilogue --------
// out_taste = 0.5 * relu(agg) + 0.5 * x_taste
#define BM 64
__global__ void __launch_bounds__(256) k6_gemm(const float* __restrict__ W,
                                               const float* __restrict__ b,
                                               const float* __restrict__ x_taste,
                                               float* __restrict__ out_taste) {
    __shared__ float xs[BM * D];     // 32KB: tile of g rows
    int tid = threadIdx.x;
    int tx  = tid & 31;              // 32 column groups of 4
    int ty  = tid >> 5;              // 8 row groups of 8 (== warp id)
    int row0 = blockIdx.x * BM;

    // load g tile (rows beyond N_TASTE -> 0)
    const float4* gsrc = (const float4*)g_gbuf;
    float4* xs4 = (float4*)xs;
    for (int i = tid; i < BM * (D / 4); i += 256) {
        int r   = i >> 5;        // row within tile
        int c4  = i & 31;        // float4 column
        int row = row0 + r;
        xs4[i] = (row < N_TASTE) ? gsrc[(size_t)row * 32 + c4]
                                 : make_float4(0.f, 0.f, 0.f, 0.f);
    }
    __syncthreads();

    float acc[8][4];
    #pragma unroll
    for (int i = 0; i < 8; i++)
        #pragma unroll
        for (int j = 0; j < 4; j++) acc[i][j] = 0.f;

    const float4* W4 = (const float4*)W;
    #pragma unroll 4
    for (int k = 0; k < D; k += 4) {
        float4 w0 = W4[(k + 0) * 32 + tx];
        float4 w1 = W4[(k + 1) * 32 + tx];
        float4 w2 = W4[(k + 2) * 32 + tx];
        float4 w3 = W4[(k + 3) * 32 + tx];
        #pragma unroll
        for (int i = 0; i < 8; i++) {
            float4 xv = xs4[(ty * 8 + i) * 32 + (k >> 2)];  // warp-broadcast LDS
            acc[i][0] += xv.x * w0.x; acc[i][1] += xv.x * w0.y; acc[i][2] += xv.x * w0.z; acc[i][3] += xv.x * w0.w;
            acc[i][0] += xv.y * w1.x; acc[i][1] += xv.y * w1.y; acc[i][2] += xv.y * w1.z; acc[i][3] += xv.y * w1.w;
            acc[i][0] += xv.z * w2.x; acc[i][1] += xv.z * w2.y; acc[i][2] += xv.z * w2.z; acc[i][3] += xv.z * w2.w;
            acc[i][0] += xv.w * w3.x; acc[i][1] += xv.w * w3.y; acc[i][2] += xv.w * w3.z; acc[i][3] += xv.w * w3.w;
        }
    }

    float4 bj = ((const float4*)b)[tx];
    #pragma unroll
    for (int i = 0; i < 8; i++) {
        int row = row0 + ty * 8 + i;
        if (row >= N_TASTE) continue;
        // segments with no incoming edges: agg row is exactly 0 (no bias)
        float has = (g_seg_sum[row] > 0.f) ? 1.0f : 0.0f;
        float4 xt = ((const float4*)x_taste)[(size_t)row * 32 + tx];
        float4 o;
        o.x = fmaxf(has * (acc[i][0] + bj.x), 0.f) * 0.5f + 0.5f * xt.x;
        o.y = fmaxf(has * (acc[i][1] + bj.y), 0.f) * 0.5f + 0.5f * xt.y;
        o.z = fmaxf(has * (acc[i][2] + bj.z), 0.f) * 0.5f + 0.5f * xt.z;
        o.w = fmaxf(has * (acc[i][3] + bj.w), 0.f) * 0.5f + 0.5f * xt.w;
        ((float4*)out_taste)[(size_t)row * 32 + tx] = o;
    }
}

// ---------------- launcher ----------------
extern "C" void kernel_launch(void* const* d_in, const int* in_sizes, int n_in,
                              void* d_out, int out_size) {
    const float* x_ing   = (const float*)d_in[0];
    const float* x_taste = (const float*)d_in[1];
    const float* W_ing   = (const float*)d_in[2];
    const float* b_ing   = (const float*)d_in[3];
    const float* W_taste = (const float*)d_in[4];
    const float* b_taste = (const float*)d_in[5];
    const float* att_src = (const float*)d_in[6];
    const float* att_dst = (const float*)d_in[7];
    // d_in[8]=Wk, d_in[9]=bk, d_in[10]=q : softmax over a single metapath == 1.0 -> unused
    const int* src_idx = (const int*)d_in[11];
    const int* dst_idx = (const int*)d_in[12];

    float* out       = (float*)d_out;
    float* out_ing   = out;                       // [N_ING, D]  == x_ing
    float* out_taste = out + (size_t)N_ING * D;   // [N_TASTE, D]

    // out_ing passthrough
    cudaMemcpyAsync(out_ing, x_ing, (size_t)N_ING * D * sizeof(float),
                    cudaMemcpyDeviceToDevice, 0);

    k0_prep<<<1, 128>>>(W_ing, b_ing, W_taste, b_taste, att_src, att_dst);
    k_init<<<1024, 256>>>();
    k_a_src<<<(N_ING + 7) / 8, 256>>>(x_ing);
    k_a_dst<<<(N_TASTE + 7) / 8, 256>>>(x_taste);
    k3_logits<<<(E_EDGES + 255) / 256, 256>>>(src_idx, dst_idx);
    k4_exp<<<(E_EDGES + 255) / 256, 256>>>(dst_idx);
    k5_scatter<<<(E_EDGES + 7) / 8, 256>>>(x_ing, src_idx, dst_idx);
    k6_gemm<<<(N_TASTE + BM - 1) / BM, 256>>>(W_ing, b_ing, x_taste, out_taste);
}